// round 6
// baseline (speedup 1.0000x reference)
#include <cuda_runtime.h>
#include <cstdint>

#define CCH   512
#define HW    49
#define CHW   (CCH * HW)          // 25088 floats per sample
#define NVEC  (CHW / 4)           // 6272 float4 per sample
#define NTHR  1024
#define EPS   1e-5f
#define TILE_BYTES (CHW * 4)      // 100352 B, 16B-multiple

// Per-thread stride in float4s = NTHR; in floats = 4096 = 83*49 + 29
#define QSTEP 83
#define RSTEP 29

__device__ __forceinline__ uint32_t smem_u32(const void* p) {
    return (uint32_t)__cvta_generic_to_shared(p);
}

__device__ __forceinline__ void bulk_load(uint32_t dst, const void* src,
                                          uint32_t bytes, uint32_t mbar) {
    asm volatile(
        "cp.async.bulk.shared::cta.global.mbarrier::complete_tx::bytes [%0], [%1], %2, [%3];"
        :: "r"(dst), "l"(src), "r"(bytes), "r"(mbar) : "memory");
}

__device__ __forceinline__ void bulk_store(void* dst, uint32_t src, uint32_t bytes) {
    asm volatile(
        "cp.async.bulk.global.shared::cta.bulk_group [%0], [%1], %2;"
        :: "l"(dst), "r"(src), "r"(bytes) : "memory");
}

__device__ __forceinline__ void mbar_expect_tx(uint32_t mbar, uint32_t bytes) {
    asm volatile("mbarrier.arrive.expect_tx.shared.b64 _, [%0], %1;"
                 :: "r"(mbar), "r"(bytes) : "memory");
}

__device__ __forceinline__ void mbar_wait(uint32_t mbar, uint32_t parity) {
    asm volatile(
        "{\n\t"
        ".reg .pred P;\n\t"
        "WAIT_LP_%=:\n\t"
        "mbarrier.try_wait.parity.acquire.cta.shared::cta.b64 P, [%0], %1, 0x989680;\n\t"
        "@P bra.uni WAIT_DN_%=;\n\t"
        "bra.uni WAIT_LP_%=;\n\t"
        "WAIT_DN_%=:\n\t"
        "}"
        :: "r"(mbar), "r"(parity) : "memory");
}

__global__ __launch_bounds__(NTHR, 2)
void gate_2cta_kernel(const float* __restrict__ x, float* __restrict__ out, int N) {
    extern __shared__ float tile[];           // CHW floats (100,352 B)
    __shared__ float part[NTHR];
    __shared__ float gateS[CCH + 8];          // pad keeps q+1 read in-bounds
    __shared__ float redA[32];
    __shared__ float redB[32];
    __shared__ __align__(8) unsigned long long mbar_store;

    const int tid = threadIdx.x;
    const uint32_t mb = smem_u32(&mbar_store);

    if (tid == 0)
        asm volatile("mbarrier.init.shared.b64 [%0], 1;" :: "r"(mb) : "memory");
    __syncthreads();

    const int stride = gridDim.x;
    uint32_t ph = 0;

    for (int s = blockIdx.x; s < N; s += stride) {
        // Issue load of sample s. Previous iteration's bulk store (same
        // buffer) must drain first; first iteration has no groups (no-op).
        if (tid == 0) {
            asm volatile("cp.async.bulk.wait_group 0;" ::: "memory");
            mbar_expect_tx(mb, TILE_BYTES);
            bulk_load(smem_u32(tile), x + (size_t)s * CHW, TILE_BYTES, mb);
        }
        mbar_wait(mb, ph);
        ph ^= 1;

        // Phase 2: per-channel partial sums, all 1024 threads.
        // Thread pair (c, c+512) splits channel c's 49 elems as 25 + 24.
        {
            const int c    = tid & (CCH - 1);
            const int half = tid >> 9;
            const float* row = tile + c * HW + half * 25;
            const int cnt  = half ? 24 : 25;
            float sacc = 0.0f;
            #pragma unroll 5
            for (int j = 0; j < cnt; j++) sacc += row[j];
            part[tid] = sacc;
        }
        __syncthreads();

        float y = 0.0f;
        if (tid < CCH) y = (part[tid] + part[tid + CCH]) * (1.0f / 49.0f);

        // Warp-level partials of sum(y), sum(y^2).
        float a = y, bb = y * y;
        #pragma unroll
        for (int off = 16; off > 0; off >>= 1) {
            a  += __shfl_xor_sync(0xffffffffu, a, off);
            bb += __shfl_xor_sync(0xffffffffu, bb, off);
        }
        const int wid = tid >> 5, lid = tid & 31;
        if (lid == 0) { redA[wid] = a; redB[wid] = bb; }
        __syncthreads();

        // Every warp redundantly reduces the 32 partials -> m, inv_std in
        // registers everywhere (no extra barrier, no broadcast roundtrip).
        a  = redA[lid];
        bb = redB[lid];
        #pragma unroll
        for (int off = 16; off > 0; off >>= 1) {
            a  += __shfl_xor_sync(0xffffffffu, a, off);
            bb += __shfl_xor_sync(0xffffffffu, bb, off);
        }
        {
            const float m   = a  * (1.0f / (float)CCH);
            const float mx2 = bb * (1.0f / (float)CCH);
            float var = mx2 - m * m;
            var = var > 0.0f ? var : 0.0f;
            const float inv = rsqrtf(var + EPS);
            if (tid < CCH) {
                const float yn = (y - m) * inv;     // gate = exp(-yn^2), C=2
                gateS[tid] = __expf(-yn * yn);
            }
        }
        __syncthreads();

        // Phase 3: gate-multiply in place in SMEM (LDS.128 -> FMUL -> STS.128).
        {
            float4* tile4 = reinterpret_cast<float4*>(tile);
            int e = tid * 4;
            int q = e / HW;          // one divide per thread per sample
            int r = e - q * HW;
            #pragma unroll 2
            for (int i = tid; i < NVEC; i += NTHR) {
                float4 v = tile4[i];
                const float g0 = gateS[q];
                const float g1 = gateS[q + 1];
                v.x *= g0;
                v.y *= (r + 1 >= HW) ? g1 : g0;
                v.z *= (r + 2 >= HW) ? g1 : g0;
                v.w *= (r + 3 >= HW) ? g1 : g0;
                tile4[i] = v;
                q += QSTEP; r += RSTEP;
                if (r >= HW) { r -= HW; q += 1; }
            }
        }
        __syncthreads();

        // Async bulk store of gated tile; drains while this CTA (and the
        // co-resident CTA) proceed. Next iteration's wait_group guards reuse.
        if (tid == 0) {
            asm volatile("fence.proxy.async.shared::cta;" ::: "memory");
            bulk_store(out + (size_t)s * CHW, smem_u32(tile), TILE_BYTES);
            asm volatile("cp.async.bulk.commit_group;" ::: "memory");
        }
    }

    if (tid == 0)
        asm volatile("cp.async.bulk.wait_group 0;" ::: "memory");
}

extern "C" void kernel_launch(void* const* d_in, const int* in_sizes, int n_in,
                              void* d_out, int out_size) {
    const float* x = (const float*)d_in[0];
    float* out = (float*)d_out;
    const int N = in_sizes[0] / CHW;   // 2048

    int sm_count = 0;
    if (cudaDeviceGetAttribute(&sm_count, cudaDevAttrMultiProcessorCount, 0)
        != cudaSuccess || sm_count <= 0)
        sm_count = 148;

    int grid = 2 * sm_count;           // 2 CTAs per SM
    if (grid > N) grid = N;

    cudaFuncSetAttribute(gate_2cta_kernel,
                         cudaFuncAttributeMaxDynamicSharedMemorySize, TILE_BYTES);
    gate_2cta_kernel<<<grid, NTHR, TILE_BYTES>>>(x, out, N);
}